// round 12
// baseline (speedup 1.0000x reference)
#include <cuda_runtime.h>
#include <cstdint>
#include <cstddef>

// Problem shape (fixed): B=8, L=4096, D=1024, DK=1024
#define BATCH 8
#define SEQ   4096
#define DIM   1024
#define NCOLS 2048
#define NROWS (BATCH * SEQ)               // 32768

// GEMM tiling: block 128x256, BK=16, 16 warps (4M x 4N), warp tile 32x64
#define BK    16
#define AROW  136                         // A smem row stride [k][m] (128 + 8)
#define BROW  264                         // B smem row stride [k][n] (256 + 8)
#define OFF_AH 0
#define OFF_AL (BK * AROW)                // 2176
#define OFF_BH (2 * BK * AROW)            // 4352
#define OFF_BL (2 * BK * AROW + BK * BROW)// 8576
#define STG    (2 * BK * AROW + 2 * BK * BROW)  // 12800 floats / stage
#define SMEM_BYTES (2 * STG * 4)          // 102400

// ---------------------------------------------------------------------------
// Scratch (no cudaMalloc allowed)
// ---------------------------------------------------------------------------
__device__ float g_qk[(size_t)NROWS * NCOLS];   // 256 MiB: [q | k] per token
__device__ float g_probs[NROWS];
__device__ int   g_bpos[NROWS];
__device__ int   g_nc[BATCH];
__device__ float g_aux[BATCH];

// ---------------------------------------------------------------------------
// Helpers
// ---------------------------------------------------------------------------
__device__ __forceinline__ float tf32_rna(float a) {
    float r;
    asm("cvt.rna.tf32.f32 %0, %1;" : "=f"(r) : "f"(a));
    return r;
}

// d += a(16x8 tf32) * b(8x8 tf32), fp32 accumulate
__device__ __forceinline__ void mma8(float* d, const uint32_t* a, const uint32_t* b) {
    asm volatile(
        "mma.sync.aligned.m16n8k8.row.col.f32.tf32.tf32.f32 "
        "{%0,%1,%2,%3}, {%4,%5,%6,%7}, {%8,%9}, {%0,%1,%2,%3};"
        : "+f"(d[0]), "+f"(d[1]), "+f"(d[2]), "+f"(d[3])
        : "r"(a[0]), "r"(a[1]), "r"(a[2]), "r"(a[3]), "r"(b[0]), "r"(b[1]));
}

// ---------------------------------------------------------------------------
// Kernel 1: 3xTF32 mma.sync GEMM   g_qk[NROWS,NCOLS] = tokens @ W
// grid (NCOLS/256=8, NROWS/128=256), 512 threads, 1 CTA/SM
// ---------------------------------------------------------------------------
__global__ void __launch_bounds__(512, 1)
gemm_mma(const float* __restrict__ A, const float* __restrict__ W)
{
    extern __shared__ float sm[];

    const int tid  = threadIdx.x;
    const int lane = tid & 31;
    const int wid  = tid >> 5;
    const int wm   = wid & 3;             // M group of 32 rows
    const int wn   = wid >> 2;            // N group of 64 cols (0..3)
    const int bm   = blockIdx.y * 128;
    const int bn   = blockIdx.x * 256;

    const int g  = lane >> 2;   // groupID
    const int tg = lane & 3;    // threadID_in_group

    float acc[2][8][4];
#pragma unroll
    for (int mt = 0; mt < 2; mt++)
#pragma unroll
        for (int nt = 0; nt < 8; nt++)
#pragma unroll
            for (int j = 0; j < 4; j++) acc[mt][nt][j] = 0.f;

    // Staging: A 128x16 -> 512 float4 -> 1/thread; B 16x256 -> 1024 float4 -> 2/thread
    float4 va, vb[2];

    auto load_regs = [&](int k0) {
        va = *reinterpret_cast<const float4*>(
            A + (size_t)(bm + (tid >> 2)) * DIM + k0 + (tid & 3) * 4);
#pragma unroll
        for (int i = 0; i < 2; i++) {
            const int c = tid + i * 512;
            vb[i] = *reinterpret_cast<const float4*>(
                W + (size_t)(k0 + (c >> 6)) * NCOLS + bn + (c & 63) * 4);
        }
    };

    auto store_smem = [&](int buf) {
        float* base = sm + buf * STG;
        // A: transpose to [k][m], split hi/lo (scalar stores)
        {
            const int m = tid >> 2, kq = tid & 3;
            float e[4] = {va.x, va.y, va.z, va.w};
#pragma unroll
            for (int j = 0; j < 4; j++) {
                float h = tf32_rna(e[j]);
                float l = tf32_rna(e[j] - h);
                base[OFF_AH + (kq * 4 + j) * AROW + m] = h;
                base[OFF_AL + (kq * 4 + j) * AROW + m] = l;
            }
        }
        // B: [k][n], split hi/lo, vector stores
#pragma unroll
        for (int i = 0; i < 2; i++) {
            const int c = tid + i * 512;
            const int k = c >> 6, n = (c & 63) * 4;
            float4 h, l;
            h.x = tf32_rna(vb[i].x); l.x = tf32_rna(vb[i].x - h.x);
            h.y = tf32_rna(vb[i].y); l.y = tf32_rna(vb[i].y - h.y);
            h.z = tf32_rna(vb[i].z); l.z = tf32_rna(vb[i].z - h.z);
            h.w = tf32_rna(vb[i].w); l.w = tf32_rna(vb[i].w - h.w);
            *reinterpret_cast<float4*>(base + OFF_BH + k * BROW + n) = h;
            *reinterpret_cast<float4*>(base + OFF_BL + k * BROW + n) = l;
        }
    };

    auto kstep = [&](const float* base, int ks) {
        const int oa1 = (ks + tg) * AROW;
        const int oa2 = (ks + 4 + tg) * AROW;
        const int ob1 = (ks + tg) * BROW;
        const int ob2 = (ks + 4 + tg) * BROW;

        const uint32_t* pAH = reinterpret_cast<const uint32_t*>(base + OFF_AH);
        const uint32_t* pAL = reinterpret_cast<const uint32_t*>(base + OFF_AL);
        const uint32_t* pBH = reinterpret_cast<const uint32_t*>(base + OFF_BH);
        const uint32_t* pBL = reinterpret_cast<const uint32_t*>(base + OFF_BL);

        uint32_t ah[2][4], al[2][4];
#pragma unroll
        for (int mt = 0; mt < 2; mt++) {
            const int m = wm * 32 + mt * 16 + g;
            ah[mt][0] = pAH[oa1 + m];     ah[mt][1] = pAH[oa1 + m + 8];
            ah[mt][2] = pAH[oa2 + m];     ah[mt][3] = pAH[oa2 + m + 8];
            al[mt][0] = pAL[oa1 + m];     al[mt][1] = pAL[oa1 + m + 8];
            al[mt][2] = pAL[oa2 + m];     al[mt][3] = pAL[oa2 + m + 8];
        }
        // B fragments short-lived: per-accumulator order stays hh -> hl -> lh
#pragma unroll
        for (int nt = 0; nt < 8; nt++) {
            const int n = wn * 64 + nt * 8 + g;
            uint32_t bh[2], bl[2];
            bh[0] = pBH[ob1 + n];  bh[1] = pBH[ob2 + n];
            bl[0] = pBL[ob1 + n];  bl[1] = pBL[ob2 + n];
#pragma unroll
            for (int mt = 0; mt < 2; mt++) mma8(acc[mt][nt], ah[mt], bh);
#pragma unroll
            for (int mt = 0; mt < 2; mt++) mma8(acc[mt][nt], ah[mt], bl);
#pragma unroll
            for (int mt = 0; mt < 2; mt++) mma8(acc[mt][nt], al[mt], bh);
        }
    };

    load_regs(0);
    store_smem(0);
    __syncthreads();

    const int NST = DIM / BK;   // 64
    for (int s = 0; s < NST; s++) {
        const int buf = s & 1;
        const float* base = sm + buf * STG;

        if (s + 1 < NST) load_regs((s + 1) * BK);
        kstep(base, 0);
        if (s + 1 < NST) store_smem(buf ^ 1);   // STS under MMA shadow
        kstep(base, 8);
        __syncthreads();
    }

    // Epilogue: C fragment -> g_qk
#pragma unroll
    for (int mt = 0; mt < 2; mt++) {
        const int r0 = bm + wm * 32 + mt * 16 + g;
#pragma unroll
        for (int nt = 0; nt < 8; nt++) {
            const int c = bn + wn * 64 + nt * 8 + tg * 2;
            *reinterpret_cast<float2*>(g_qk + (size_t)r0 * NCOLS + c) =
                make_float2(acc[mt][nt][0], acc[mt][nt][1]);
            *reinterpret_cast<float2*>(g_qk + (size_t)(r0 + 8) * NCOLS + c) =
                make_float2(acc[mt][nt][2], acc[mt][nt][3]);
        }
    }
}

// ---------------------------------------------------------------------------
// Kernel 2: one warp per token — cosine(q_l, k_{l-1}) -> probs
// ---------------------------------------------------------------------------
__global__ void cos_kernel(const float* __restrict__ start_key)
{
    const int gw   = (blockIdx.x * blockDim.x + threadIdx.x) >> 5;
    const int lane = threadIdx.x & 31;
    if (gw >= NROWS) return;
    const int l = gw & (SEQ - 1);

    const float4* q = reinterpret_cast<const float4*>(g_qk + (size_t)gw * NCOLS);
    const float4* kp = (l == 0)
        ? reinterpret_cast<const float4*>(start_key)
        : reinterpret_cast<const float4*>(g_qk + (size_t)(gw - 1) * NCOLS + DIM);

    float dot = 0.f, qq = 0.f, kk = 0.f;
#pragma unroll
    for (int i = 0; i < 8; i++) {
        float4 qv = q[lane + i * 32];
        float4 kv = kp[lane + i * 32];
        dot += qv.x * kv.x + qv.y * kv.y + qv.z * kv.z + qv.w * kv.w;
        qq  += qv.x * qv.x + qv.y * qv.y + qv.z * qv.z + qv.w * qv.w;
        kk  += kv.x * kv.x + kv.y * kv.y + kv.z * kv.z + kv.w * kv.w;
    }
#pragma unroll
    for (int o = 16; o; o >>= 1) {
        dot += __shfl_xor_sync(0xffffffffu, dot, o);
        qq  += __shfl_xor_sync(0xffffffffu, qq,  o);
        kk  += __shfl_xor_sync(0xffffffffu, kk,  o);
    }
    if (lane == 0) {
        float qn = fmaxf(sqrtf(qq), 1e-8f);
        float kn = fmaxf(sqrtf(kk), 1e-8f);
        float cs = dot / (qn * kn);
        g_probs[gw] = (1.0f - cs) * 0.5f;
    }
}

// ---------------------------------------------------------------------------
// Kernel 3: per-batch boundary scan/compaction, chunk_lens, aux partials
// ---------------------------------------------------------------------------
__global__ void __launch_bounds__(1024, 1)
scan_kernel(float* __restrict__ out_cl)
{
    const int b = blockIdx.x;
    const int tid = threadIdx.x;
    const int lane = tid & 31, wid = tid >> 5;

    __shared__ int   warp_c[32];
    __shared__ float warp_s[32];
    __shared__ int   s_nc;
    __shared__ float s_G;

    const float* pr = g_probs + b * SEQ;
    float4 p4 = reinterpret_cast<const float4*>(pr)[tid];
    float p[4] = {p4.x, p4.y, p4.z, p4.w};

    int m[4]; int cnt = 0; float psum = 0.f;
#pragma unroll
    for (int i = 0; i < 4; i++) {
        int l = tid * 4 + i;
        m[i] = (p[i] > 0.5f) || (l == 0);
        cnt += m[i];
        psum += p[i];
    }

    int inc = cnt;
#pragma unroll
    for (int o = 1; o < 32; o <<= 1) {
        int v = __shfl_up_sync(0xffffffffu, inc, o);
        if (lane >= o) inc += v;
    }
    float ws = psum;
#pragma unroll
    for (int o = 16; o; o >>= 1) ws += __shfl_xor_sync(0xffffffffu, ws, o);

    if (lane == 31) warp_c[wid] = inc;
    if (lane == 0)  warp_s[wid] = ws;
    __syncthreads();

    if (wid == 0) {
        int v = warp_c[lane];
        int iv = v;
#pragma unroll
        for (int o = 1; o < 32; o <<= 1) {
            int t = __shfl_up_sync(0xffffffffu, iv, o);
            if (lane >= o) iv += t;
        }
        float s = warp_s[lane];
#pragma unroll
        for (int o = 16; o; o >>= 1) s += __shfl_xor_sync(0xffffffffu, s, o);
        warp_c[lane] = iv - v;
        if (lane == 31) s_nc = iv;
        if (lane == 0)  s_G  = s;
    }
    __syncthreads();

    int r = warp_c[wid] + (inc - cnt);
#pragma unroll
    for (int i = 0; i < 4; i++) {
        if (m[i]) { g_bpos[b * SEQ + r] = tid * 4 + i; r++; }
    }
    const int nc = s_nc;
    if (tid == 0) {
        g_nc[b] = nc;
        float G  = s_G / (float)SEQ;
        float Fm = (float)nc / (float)SEQ;
        g_aux[b] = 1.2f * (5.0f * Fm * G + (1.0f - Fm) * (1.0f - G));
    }
    __syncthreads();

#pragma unroll
    for (int i = 0; i < 4; i++) {
        int j = tid * 4 + i;
        float v = 0.f;
        if (j < nc) {
            int pj = g_bpos[b * SEQ + j];
            int pn = (j + 1 < nc) ? g_bpos[b * SEQ + j + 1] : SEQ;
            v = (float)(pn - pj);
        }
        out_cl[b * SEQ + j] = v;
    }
}

// ---------------------------------------------------------------------------
// Kernel 4: downsampled gather + scalar loss
// ---------------------------------------------------------------------------
__global__ void gather_kernel(const float* __restrict__ tokens,
                              float* __restrict__ out_ds,
                              float* __restrict__ out_loss)
{
    const int row = blockIdx.x;
    const int b = row >> 12;
    const int j = row & (SEQ - 1);
    const int tid = threadIdx.x;

    float4* dst = reinterpret_cast<float4*>(out_ds + (size_t)row * DIM);
    if (j < g_nc[b]) {
        int   p = g_bpos[b * SEQ + j];
        float s = g_probs[b * SEQ + p];
        const float4* src = reinterpret_cast<const float4*>(
            tokens + (size_t)(b * SEQ + p) * DIM);
        float4 v0 = src[tid], v1 = src[tid + 128];
        dst[tid]       = make_float4(v0.x * s, v0.y * s, v0.z * s, v0.w * s);
        dst[tid + 128] = make_float4(v1.x * s, v1.y * s, v1.z * s, v1.w * s);
    } else {
        float4 z = make_float4(0.f, 0.f, 0.f, 0.f);
        dst[tid] = z; dst[tid + 128] = z;
    }

    if (row == 0 && tid == 0) {
        float s = 0.f;
#pragma unroll
        for (int i = 0; i < BATCH; i++) s += g_aux[i];
        *out_loss = s * (0.03f / (float)BATCH);
    }
}

// ---------------------------------------------------------------------------
// Launch
// ---------------------------------------------------------------------------
extern "C" void kernel_launch(void* const* d_in, const int* in_sizes, int n_in,
                              void* d_out, int out_size)
{
    const float* tokens    = (const float*)d_in[0];
    const float* W_qk      = (const float*)d_in[1];
    const float* start_key = (const float*)d_in[2];

    float* out      = (float*)d_out;
    float* out_ds   = out;
    float* out_cl   = out + (size_t)NROWS * DIM;
    float* out_loss = out_cl + NROWS;

    cudaFuncSetAttribute(gemm_mma, cudaFuncAttributeMaxDynamicSharedMemorySize,
                         SMEM_BYTES);

    dim3 grid(NCOLS / 256, NROWS / 128);   // (8, 256)
    gemm_mma<<<grid, 512, SMEM_BYTES>>>(tokens, W_qk);
    cos_kernel<<<NROWS / 8, 256>>>(start_key);
    scan_kernel<<<BATCH, 1024>>>(out_cl);
    gather_kernel<<<NROWS, 128>>>(tokens, out_ds, out_loss);

    (void)in_sizes; (void)n_in; (void)out_size;
}

// round 13
// speedup vs baseline: 1.7427x; 1.7427x over previous
#include <cuda_runtime.h>
#include <cuda_fp16.h>
#include <cstdint>
#include <cstddef>

// Problem shape (fixed): B=8, L=4096, D=1024, DK=1024
#define BATCH 8
#define SEQ   4096
#define DIM   1024
#define NCOLS 2048
#define NROWS (BATCH * SEQ)               // 32768

// GEMM tiling: block 128x128, BK=16 (one k16 mma-step per stage), 8 warps (4Mx2N)
// Smem tiles stored as half2 (k-pairs packed): [8 k2][KROW] per tile.
#define KROW   136                        // half2 units per k2-row (128 + 8 pad)
#define OFF_AH 0
#define OFF_AL (8 * KROW)                 // 1088
#define OFF_BH (16 * KROW)                // 2176
#define OFF_BL (24 * KROW)                // 3264
#define STG    (32 * KROW)                // 4352 half2 units per stage
#define SMEM_BYTES (2 * STG * 4)          // 34816

// ---------------------------------------------------------------------------
// Scratch (no cudaMalloc allowed)
// ---------------------------------------------------------------------------
__device__ float g_qk[(size_t)NROWS * NCOLS];   // 256 MiB: [q | k] per token
__device__ float g_probs[NROWS];
__device__ int   g_bpos[NROWS];
__device__ int   g_nc[BATCH];
__device__ float g_aux[BATCH];

// ---------------------------------------------------------------------------
// Helpers
// ---------------------------------------------------------------------------
// pack two floats (lo, hi) into f16x2 with rn
__device__ __forceinline__ uint32_t f2h2(float lo, float hi) {
    half2 h = __floats2half2_rn(lo, hi);
    return *reinterpret_cast<uint32_t*>(&h);
}
__device__ __forceinline__ float h1f(float a) {           // fp16 rounding of a
    return __half2float(__float2half_rn(a));
}

// d += a(16x16 f16) * b(16x8 f16), fp32 accumulate
__device__ __forceinline__ void mma16(float* d, const uint32_t* a, const uint32_t* b) {
    asm volatile(
        "mma.sync.aligned.m16n8k16.row.col.f32.f16.f16.f32 "
        "{%0,%1,%2,%3}, {%4,%5,%6,%7}, {%8,%9}, {%0,%1,%2,%3};"
        : "+f"(d[0]), "+f"(d[1]), "+f"(d[2]), "+f"(d[3])
        : "r"(a[0]), "r"(a[1]), "r"(a[2]), "r"(a[3]), "r"(b[0]), "r"(b[1]));
}

// ---------------------------------------------------------------------------
// Kernel 1: 3-pass fp16-split GEMM  g_qk[NROWS,NCOLS] = tokens @ W  (fp32 acc)
// grid (NCOLS/128=16, NROWS/128=256), 256 threads
// ---------------------------------------------------------------------------
__global__ void __launch_bounds__(256, 1)
gemm_mma(const float* __restrict__ A, const float* __restrict__ W)
{
    extern __shared__ uint32_t sm[];      // half2 units

    const int tid  = threadIdx.x;
    const int lane = tid & 31;
    const int wid  = tid >> 5;
    const int wm   = wid & 3;             // M group of 32 rows
    const int wn   = wid >> 2;            // N group of 64 cols
    const int bm   = blockIdx.y * 128;
    const int bn   = blockIdx.x * 128;

    const int g  = lane >> 2;   // groupID
    const int tg = lane & 3;    // threadID_in_group

    float acc[2][8][4];
#pragma unroll
    for (int mt = 0; mt < 2; mt++)
#pragma unroll
        for (int nt = 0; nt < 8; nt++)
#pragma unroll
            for (int j = 0; j < 4; j++) acc[mt][nt][j] = 0.f;

    // Staging: A 128x16 floats = 512 float4 -> 2/thread (row=c>>2, kq=c&3)
    //          B 16x128 floats: per thread one (j, n4) group needing rows 2j, 2j+1
    float4 va[2], vb0, vb1;
    const int bj  = tid >> 5;             // k2 index 0..7
    const int bn4 = (tid & 31) * 4;       // n offset 0..124

    auto load_regs = [&](int k0) {
#pragma unroll
        for (int i = 0; i < 2; i++) {
            const int c = tid + i * 256;
            va[i] = *reinterpret_cast<const float4*>(
                A + (size_t)(bm + (c >> 2)) * DIM + k0 + (c & 3) * 4);
        }
        vb0 = *reinterpret_cast<const float4*>(
            W + (size_t)(k0 + 2 * bj) * NCOLS + bn + bn4);
        vb1 = *reinterpret_cast<const float4*>(
            W + (size_t)(k0 + 2 * bj + 1) * NCOLS + bn + bn4);
    };

    auto store_smem = [&](int buf) {
        uint32_t* base = sm + buf * STG;
        // A: [k2][m] half2 (k pairs within a row), hi/lo split
#pragma unroll
        for (int i = 0; i < 2; i++) {
            const int c = tid + i * 256;
            const int row = c >> 2, kq = c & 3;
            float e[4] = {va[i].x, va[i].y, va[i].z, va[i].w};
            float h[4], l[4];
#pragma unroll
            for (int j = 0; j < 4; j++) { h[j] = h1f(e[j]); l[j] = e[j] - h[j]; }
            base[OFF_AH + (2 * kq + 0) * KROW + row] = f2h2(h[0], h[1]);
            base[OFF_AH + (2 * kq + 1) * KROW + row] = f2h2(h[2], h[3]);
            base[OFF_AL + (2 * kq + 0) * KROW + row] = f2h2(l[0], l[1]);
            base[OFF_AL + (2 * kq + 1) * KROW + row] = f2h2(l[2], l[3]);
        }
        // B: [k2][n] half2 (k pair 2j,2j+1 for same n), hi/lo split, 16B stores
        {
            float r0[4] = {vb0.x, vb0.y, vb0.z, vb0.w};
            float r1[4] = {vb1.x, vb1.y, vb1.z, vb1.w};
            uint32_t hh[4], ll[4];
#pragma unroll
            for (int j = 0; j < 4; j++) {
                float h0 = h1f(r0[j]), h1 = h1f(r1[j]);
                hh[j] = f2h2(h0, h1);
                ll[j] = f2h2(r0[j] - h0, r1[j] - h1);
            }
            *reinterpret_cast<uint4*>(base + OFF_BH + bj * KROW + bn4) =
                make_uint4(hh[0], hh[1], hh[2], hh[3]);
            *reinterpret_cast<uint4*>(base + OFF_BL + bj * KROW + bn4) =
                make_uint4(ll[0], ll[1], ll[2], ll[3]);
        }
    };

    load_regs(0);
    store_smem(0);
    __syncthreads();

    const int NST = DIM / 16;   // 64 stages, one k16 step each
    for (int s = 0; s < NST; s++) {
        const int buf = s & 1;
        const uint32_t* base = sm + buf * STG;

        if (s + 1 < NST) load_regs((s + 1) * 16);

        // Fragment loads (conflict-free: bank = 8*tg + g + const)
        const uint32_t* pAH = base + OFF_AH;
        const uint32_t* pAL = base + OFF_AL;
        const uint32_t* pBH = base + OFF_BH;
        const uint32_t* pBL = base + OFF_BL;

        uint32_t ah[2][4], al[2][4], bh[8][2], bl[8][2];
#pragma unroll
        for (int mt = 0; mt < 2; mt++) {
            const int m = wm * 32 + mt * 16 + g;
            ah[mt][0] = pAH[tg * KROW + m];
            ah[mt][1] = pAH[tg * KROW + m + 8];
            ah[mt][2] = pAH[(tg + 4) * KROW + m];
            ah[mt][3] = pAH[(tg + 4) * KROW + m + 8];
            al[mt][0] = pAL[tg * KROW + m];
            al[mt][1] = pAL[tg * KROW + m + 8];
            al[mt][2] = pAL[(tg + 4) * KROW + m];
            al[mt][3] = pAL[(tg + 4) * KROW + m + 8];
        }
#pragma unroll
        for (int nt = 0; nt < 8; nt++) {
            const int n = wn * 64 + nt * 8 + g;
            bh[nt][0] = pBH[tg * KROW + n];
            bh[nt][1] = pBH[(tg + 4) * KROW + n];
            bl[nt][0] = pBL[tg * KROW + n];
            bl[nt][1] = pBL[(tg + 4) * KROW + n];
        }

        // pass 1: hi*hi
#pragma unroll
        for (int nt = 0; nt < 8; nt++)
#pragma unroll
            for (int mt = 0; mt < 2; mt++) mma16(acc[mt][nt], ah[mt], bh[nt]);

        if (s + 1 < NST) store_smem(buf ^ 1);   // STS under MMA shadow

        // pass 2: hi*lo
#pragma unroll
        for (int nt = 0; nt < 8; nt++)
#pragma unroll
            for (int mt = 0; mt < 2; mt++) mma16(acc[mt][nt], ah[mt], bl[nt]);
        // pass 3: lo*hi
#pragma unroll
        for (int nt = 0; nt < 8; nt++)
#pragma unroll
            for (int mt = 0; mt < 2; mt++) mma16(acc[mt][nt], al[mt], bh[nt]);

        __syncthreads();
    }

    // Epilogue: C fragment -> g_qk
#pragma unroll
    for (int mt = 0; mt < 2; mt++) {
        const int r0 = bm + wm * 32 + mt * 16 + g;
#pragma unroll
        for (int nt = 0; nt < 8; nt++) {
            const int c = bn + wn * 64 + nt * 8 + tg * 2;
            *reinterpret_cast<float2*>(g_qk + (size_t)r0 * NCOLS + c) =
                make_float2(acc[mt][nt][0], acc[mt][nt][1]);
            *reinterpret_cast<float2*>(g_qk + (size_t)(r0 + 8) * NCOLS + c) =
                make_float2(acc[mt][nt][2], acc[mt][nt][3]);
        }
    }
}

// ---------------------------------------------------------------------------
// Kernel 2: one warp per token — cosine(q_l, k_{l-1}) -> probs
// ---------------------------------------------------------------------------
__global__ void cos_kernel(const float* __restrict__ start_key)
{
    const int gw   = (blockIdx.x * blockDim.x + threadIdx.x) >> 5;
    const int lane = threadIdx.x & 31;
    if (gw >= NROWS) return;
    const int l = gw & (SEQ - 1);

    const float4* q = reinterpret_cast<const float4*>(g_qk + (size_t)gw * NCOLS);
    const float4* kp = (l == 0)
        ? reinterpret_cast<const float4*>(start_key)
        : reinterpret_cast<const float4*>(g_qk + (size_t)(gw - 1) * NCOLS + DIM);

    float dot = 0.f, qq = 0.f, kk = 0.f;
#pragma unroll
    for (int i = 0; i < 8; i++) {
        float4 qv = q[lane + i * 32];
        float4 kv = kp[lane + i * 32];
        dot += qv.x * kv.x + qv.y * kv.y + qv.z * kv.z + qv.w * kv.w;
        qq  += qv.x * qv.x + qv.y * qv.y + qv.z * qv.z + qv.w * qv.w;
        kk  += kv.x * kv.x + kv.y * kv.y + kv.z * kv.z + kv.w * kv.w;
    }
#pragma unroll
    for (int o = 16; o; o >>= 1) {
        dot += __shfl_xor_sync(0xffffffffu, dot, o);
        qq  += __shfl_xor_sync(0xffffffffu, qq,  o);
        kk  += __shfl_xor_sync(0xffffffffu, kk,  o);
    }
    if (lane == 0) {
        float qn = fmaxf(sqrtf(qq), 1e-8f);
        float kn = fmaxf(sqrtf(kk), 1e-8f);
        float cs = dot / (qn * kn);
        g_probs[gw] = (1.0f - cs) * 0.5f;
    }
}

// ---------------------------------------------------------------------------
// Kernel 3: per-batch boundary scan/compaction, chunk_lens, aux partials
// ---------------------------------------------------------------------------
__global__ void __launch_bounds__(1024, 1)
scan_kernel(float* __restrict__ out_cl)
{
    const int b = blockIdx.x;
    const int tid = threadIdx.x;
    const int lane = tid & 31, wid = tid >> 5;

    __shared__ int   warp_c[32];
    __shared__ float warp_s[32];
    __shared__ int   s_nc;
    __shared__ float s_G;

    const float* pr = g_probs + b * SEQ;
    float4 p4 = reinterpret_cast<const float4*>(pr)[tid];
    float p[4] = {p4.x, p4.y, p4.z, p4.w};

    int m[4]; int cnt = 0; float psum = 0.f;
#pragma unroll
    for (int i = 0; i < 4; i++) {
        int l = tid * 4 + i;
        m[i] = (p[i] > 0.5f) || (l == 0);
        cnt += m[i];
        psum += p[i];
    }

    int inc = cnt;
#pragma unroll
    for (int o = 1; o < 32; o <<= 1) {
        int v = __shfl_up_sync(0xffffffffu, inc, o);
        if (lane >= o) inc += v;
    }
    float ws = psum;
#pragma unroll
    for (int o = 16; o; o >>= 1) ws += __shfl_xor_sync(0xffffffffu, ws, o);

    if (lane == 31) warp_c[wid] = inc;
    if (lane == 0)  warp_s[wid] = ws;
    __syncthreads();

    if (wid == 0) {
        int v = warp_c[lane];
        int iv = v;
#pragma unroll
        for (int o = 1; o < 32; o <<= 1) {
            int t = __shfl_up_sync(0xffffffffu, iv, o);
            if (lane >= o) iv += t;
        }
        float s = warp_s[lane];
#pragma unroll
        for (int o = 16; o; o >>= 1) s += __shfl_xor_sync(0xffffffffu, s, o);
        warp_c[lane] = iv - v;
        if (lane == 31) s_nc = iv;
        if (lane == 0)  s_G  = s;
    }
    __syncthreads();

    int r = warp_c[wid] + (inc - cnt);
#pragma unroll
    for (int i = 0; i < 4; i++) {
        if (m[i]) { g_bpos[b * SEQ + r] = tid * 4 + i; r++; }
    }
    const int nc = s_nc;
    if (tid == 0) {
        g_nc[b] = nc;
        float G  = s_G / (float)SEQ;
        float Fm = (float)nc / (float)SEQ;
        g_aux[b] = 1.2f * (5.0f * Fm * G + (1.0f - Fm) * (1.0f - G));
    }
    __syncthreads();

#pragma unroll
    for (int i = 0; i < 4; i++) {
        int j = tid * 4 + i;
        float v = 0.f;
        if (j < nc) {
            int pj = g_bpos[b * SEQ + j];
            int pn = (j + 1 < nc) ? g_bpos[b * SEQ + j + 1] : SEQ;
            v = (float)(pn - pj);
        }
        out_cl[b * SEQ + j] = v;
    }
}

// ---------------------------------------------------------------------------
// Kernel 4: downsampled gather + scalar loss
// ---------------------------------------------------------------------------
__global__ void gather_kernel(const float* __restrict__ tokens,
                              float* __restrict__ out_ds,
                              float* __restrict__ out_loss)
{
    const int row = blockIdx.x;
    const int b = row >> 12;
    const int j = row & (SEQ - 1);
    const int tid = threadIdx.x;

    float4* dst = reinterpret_cast<float4*>(out_ds + (size_t)row * DIM);
    if (j < g_nc[b]) {
        int   p = g_bpos[b * SEQ + j];
        float s = g_probs[b * SEQ + p];
        const float4* src = reinterpret_cast<const float4*>(
            tokens + (size_t)(b * SEQ + p) * DIM);
        float4 v0 = src[tid], v1 = src[tid + 128];
        dst[tid]       = make_float4(v0.x * s, v0.y * s, v0.z * s, v0.w * s);
        dst[tid + 128] = make_float4(v1.x * s, v1.y * s, v1.z * s, v1.w * s);
    } else {
        float4 z = make_float4(0.f, 0.f, 0.f, 0.f);
        dst[tid] = z; dst[tid + 128] = z;
    }

    if (row == 0 && tid == 0) {
        float s = 0.f;
#pragma unroll
        for (int i = 0; i < BATCH; i++) s += g_aux[i];
        *out_loss = s * (0.03f / (float)BATCH);
    }
}

// ---------------------------------------------------------------------------
// Launch
// ---------------------------------------------------------------------------
extern "C" void kernel_launch(void* const* d_in, const int* in_sizes, int n_in,
                              void* d_out, int out_size)
{
    const float* tokens    = (const float*)d_in[0];
    const float* W_qk      = (const float*)d_in[1];
    const float* start_key = (const float*)d_in[2];

    float* out      = (float*)d_out;
    float* out_ds   = out;
    float* out_cl   = out + (size_t)NROWS * DIM;
    float* out_loss = out_cl + NROWS;

    cudaFuncSetAttribute(gemm_mma, cudaFuncAttributeMaxDynamicSharedMemorySize,
                         SMEM_BYTES);

    dim3 grid(NCOLS / 128, NROWS / 128);   // (16, 256)
    gemm_mma<<<grid, 256, SMEM_BYTES>>>(tokens, W_qk);
    cos_kernel<<<NROWS / 8, 256>>>(start_key);
    scan_kernel<<<BATCH, 1024>>>(out_cl);
    gather_kernel<<<NROWS, 128>>>(tokens, out_ds, out_loss);

    (void)in_sizes; (void)n_in; (void)out_size;
}